// round 1
// baseline (speedup 1.0000x reference)
#include <cuda_runtime.h>

#define BATCH 8
#define CH    512
#define DD    64
#define NN    4096
#define EPSF  1e-10f

// Scratch (allocation-free rule: __device__ globals)
__device__ float g_Qf[BATCH * DD * NN];    // delu(Q), [b][d][n]
__device__ float g_Kf[BATCH * DD * NN];    // delu(K), [b][d][n]
__device__ float g_KXt[BATCH * DD * CH];   // Kf @ x^T, [b][d][c]
__device__ float g_KV[BATCH * DD * CH];    // KXt @ wv^T + bias, [b][d][c]
__device__ float g_Ksum[BATCH * DD];       // sum_n Kf + EPS

__device__ __forceinline__ float delu(float v) {
    return 10.0f * fmaxf(v, 0.0f) + __expf(10.0f * fminf(v, 0.0f));
}

// ---------------------------------------------------------------------------
// 0) init: zero accumulators, Ksum = EPS
// ---------------------------------------------------------------------------
__global__ void init_kernel() {
    int i = blockIdx.x * blockDim.x + threadIdx.x;
    if (i < BATCH * DD * CH) { g_KXt[i] = 0.0f; g_KV[i] = 0.0f; }
    if (i < BATCH * DD) g_Ksum[i] = EPSF;
}

// ---------------------------------------------------------------------------
// 1) Fused Q/K projection + delu.
//    Per block: M=128 (rows 0..63 = wq, 64..127 = wk) x N=128 tile, K=512.
//    grid = (NN/128, BATCH), 256 threads, 8x8 micro-tile.
// ---------------------------------------------------------------------------
__global__ __launch_bounds__(256) void qk_kernel(
    const float* __restrict__ x, const float* __restrict__ wq,
    const float* __restrict__ bq, const float* __restrict__ wk,
    const float* __restrict__ bk)
{
    __shared__ float As[32][129];  // [k][m], padded for conflict-free transpose write
    __shared__ float Bs[32][128];  // [k][n]
    const int b  = blockIdx.y;
    const int n0 = blockIdx.x * 128;
    const int t  = threadIdx.x;
    const int tx = t & 15, ty = t >> 4;
    const float* xb = x + (size_t)b * CH * NN;

    float acc[8][8];
#pragma unroll
    for (int i = 0; i < 8; i++)
#pragma unroll
        for (int j = 0; j < 8; j++) acc[i][j] = 0.0f;

    for (int k0 = 0; k0 < CH; k0 += 32) {
#pragma unroll
        for (int r = 0; r < 16; r++) {           // A: 128 rows x 32 k
            int idx = t + r * 256;
            int m = idx >> 5, kk = idx & 31;
            const float* wsrc = (m < 64) ? (wq + (size_t)m * CH)
                                         : (wk + (size_t)(m - 64) * CH);
            As[kk][m] = wsrc[k0 + kk];
        }
#pragma unroll
        for (int r = 0; r < 16; r++) {           // B: 32 k x 128 n
            int idx = t + r * 256;
            int kk = idx >> 7, n = idx & 127;
            Bs[kk][n] = xb[(size_t)(k0 + kk) * NN + n0 + n];
        }
        __syncthreads();
#pragma unroll
        for (int kk = 0; kk < 32; kk++) {
            float a[8], bb[8];
#pragma unroll
            for (int i = 0; i < 8; i++) a[i] = As[kk][ty * 8 + i];
#pragma unroll
            for (int j = 0; j < 8; j++) bb[j] = Bs[kk][tx * 8 + j];
#pragma unroll
            for (int i = 0; i < 8; i++)
#pragma unroll
                for (int j = 0; j < 8; j++) acc[i][j] += a[i] * bb[j];
        }
        __syncthreads();
    }

#pragma unroll
    for (int i = 0; i < 8; i++) {
        int m = ty * 8 + i;
        float bias;
        float* dst;
        if (m < 64) { bias = bq[m];      dst = g_Qf + ((size_t)b * DD + m)      * NN + n0; }
        else        { bias = bk[m - 64]; dst = g_Kf + ((size_t)b * DD + m - 64) * NN + n0; }
#pragma unroll
        for (int j = 0; j < 8; j++)
            dst[tx * 8 + j] = delu(acc[i][j] + bias);
    }
}

// ---------------------------------------------------------------------------
// 2) KXt[b,m,c] += sum_n Kf[b,m,n] * x[b,c,n]  (N split into 8 chunks of 512)
//    Also accumulates Ksum[b,m] (blocks with e-tile 0).
//    grid = (CH/128, 8, BATCH), 256 threads, 64x128 tile, 8x4 micro.
// ---------------------------------------------------------------------------
__global__ __launch_bounds__(256) void kxt_kernel(const float* __restrict__ x)
{
    __shared__ float As[32][65];   // [n][m]
    __shared__ float Bs[32][129];  // [n][c]
    const int b  = blockIdx.z;
    const int nb = blockIdx.y * 512;
    const int e0 = blockIdx.x * 128;
    const int t  = threadIdx.x;
    const int tx = t & 31, ty = t >> 5;
    const float* kf = g_Kf + (size_t)b * DD * NN;
    const float* xb = x + (size_t)b * CH * NN;

    float acc[8][4];
#pragma unroll
    for (int i = 0; i < 8; i++)
#pragma unroll
        for (int j = 0; j < 4; j++) acc[i][j] = 0.0f;

    for (int k0 = 0; k0 < 512; k0 += 32) {
        const int nbase = nb + k0;
#pragma unroll
        for (int r = 0; r < 8; r++) {            // A: 64 m x 32 n
            int idx = t + r * 256;
            int m = idx >> 5, kk = idx & 31;
            As[kk][m] = kf[(size_t)m * NN + nbase + kk];
        }
#pragma unroll
        for (int r = 0; r < 16; r++) {           // B: 128 c x 32 n
            int idx = t + r * 256;
            int e = idx >> 5, kk = idx & 31;
            Bs[kk][e] = xb[(size_t)(e0 + e) * NN + nbase + kk];
        }
        __syncthreads();
#pragma unroll
        for (int kk = 0; kk < 32; kk++) {
            float a[8], bb[4];
#pragma unroll
            for (int i = 0; i < 8; i++) a[i] = As[kk][ty * 8 + i];
#pragma unroll
            for (int j = 0; j < 4; j++) bb[j] = Bs[kk][tx * 4 + j];
#pragma unroll
            for (int i = 0; i < 8; i++)
#pragma unroll
                for (int j = 0; j < 4; j++) acc[i][j] += a[i] * bb[j];
        }
        __syncthreads();
    }

    float* kxt = g_KXt + (size_t)b * DD * CH;
#pragma unroll
    for (int i = 0; i < 8; i++) {
        int m = ty * 8 + i;
#pragma unroll
        for (int j = 0; j < 4; j++)
            atomicAdd(&kxt[(size_t)m * CH + e0 + tx * 4 + j], acc[i][j]);
    }

    // Ksum partials (one e-tile's blocks only)
    if (blockIdx.x == 0) {
        const int w = t >> 5, lane = t & 31;
#pragma unroll
        for (int rr = 0; rr < 8; rr++) {
            int m = w * 8 + rr;
            float s = 0.0f;
            for (int n = lane; n < 512; n += 32)
                s += kf[(size_t)m * NN + nb + n];
#pragma unroll
            for (int off = 16; off > 0; off >>= 1)
                s += __shfl_down_sync(0xffffffffu, s, off);
            if (lane == 0) atomicAdd(&g_Ksum[b * DD + m], s);
        }
    }
}

// ---------------------------------------------------------------------------
// 3) KV = KXt_flat[512,512] @ wv^T + (Ksum-EPS)*bv.  K split into 4 chunks.
//    grid = (CH/128, 8, 4), 256 threads, 64x128 tile.
// ---------------------------------------------------------------------------
__global__ __launch_bounds__(256) void kv_kernel(
    const float* __restrict__ wv, const float* __restrict__ bv)
{
    __shared__ float As[32][65];
    __shared__ float Bs[32][129];
    const int e0 = blockIdx.x * 128;
    const int m0 = blockIdx.y * 64;      // global row in [0, B*DD)
    const int c0 = blockIdx.z * 128;     // K-split chunk
    const int t  = threadIdx.x;
    const int tx = t & 31, ty = t >> 5;

    float acc[8][4];
#pragma unroll
    for (int i = 0; i < 8; i++)
#pragma unroll
        for (int j = 0; j < 4; j++) acc[i][j] = 0.0f;

    for (int k0 = c0; k0 < c0 + 128; k0 += 32) {
#pragma unroll
        for (int r = 0; r < 8; r++) {
            int idx = t + r * 256;
            int m = idx >> 5, kk = idx & 31;
            As[kk][m] = g_KXt[(size_t)(m0 + m) * CH + k0 + kk];
        }
#pragma unroll
        for (int r = 0; r < 16; r++) {
            int idx = t + r * 256;
            int e = idx >> 5, kk = idx & 31;
            Bs[kk][e] = wv[(size_t)(e0 + e) * CH + k0 + kk];
        }
        __syncthreads();
#pragma unroll
        for (int kk = 0; kk < 32; kk++) {
            float a[8], bb[4];
#pragma unroll
            for (int i = 0; i < 8; i++) a[i] = As[kk][ty * 8 + i];
#pragma unroll
            for (int j = 0; j < 4; j++) bb[j] = Bs[kk][tx * 4 + j];
#pragma unroll
            for (int i = 0; i < 8; i++)
#pragma unroll
                for (int j = 0; j < 4; j++) acc[i][j] += a[i] * bb[j];
        }
        __syncthreads();
    }

#pragma unroll
    for (int i = 0; i < 8; i++) {
        int m = m0 + ty * 8 + i;
#pragma unroll
        for (int j = 0; j < 4; j++) {
            int e = e0 + tx * 4 + j;
            float v = acc[i][j];
            if (blockIdx.z == 0) v += (g_Ksum[m] - EPSF) * bv[e];
            atomicAdd(&g_KV[(size_t)m * CH + e], v);
        }
    }
}

// ---------------------------------------------------------------------------
// 4) out = x + gamma * norm[n] * (Qf^T @ KV).  K = 64.
//    norm[n] = 1 / sum_d Qf[b,d,n]*Ksum[b,d]  (Ksum already includes EPS)
//    grid = (NN/128, CH/128, BATCH), 256 threads, dynamic smem.
// ---------------------------------------------------------------------------
__global__ __launch_bounds__(256) void out_kernel(
    const float* __restrict__ x, const float* __restrict__ gamma,
    float* __restrict__ out)
{
    extern __shared__ float sm[];
    float* Qs    = sm;                 // [64][128]  Qf tile
    float* Vs    = sm + 64 * 128;      // [64][128]  KV tile
    float* Ks    = Vs + 64 * 128;      // [64]
    float* normv = Ks + 64;            // [128]

    const int b  = blockIdx.z;
    const int c0 = blockIdx.y * 128;
    const int n0 = blockIdx.x * 128;
    const int t  = threadIdx.x;
    const int tx = t & 15, ty = t >> 4;
    const float* qf = g_Qf + (size_t)b * DD * NN;
    const float* kv = g_KV + (size_t)b * DD * CH;

#pragma unroll
    for (int r = 0; r < 32; r++) {
        int idx = t + r * 256;
        int d = idx >> 7, n = idx & 127;
        Qs[d * 128 + n] = qf[(size_t)d * NN + n0 + n];
    }
#pragma unroll
    for (int r = 0; r < 32; r++) {
        int idx = t + r * 256;
        int d = idx >> 7, cc = idx & 127;
        Vs[d * 128 + cc] = kv[(size_t)d * CH + c0 + cc];
    }
    if (t < 64) Ks[t] = g_Ksum[b * DD + t];
    __syncthreads();

    if (t < 128) {
        float s = 0.0f;
#pragma unroll
        for (int d = 0; d < 64; d++) s += Qs[d * 128 + t] * Ks[d];
        normv[t] = 1.0f / s;
    }
    __syncthreads();

    float acc[8][8];
#pragma unroll
    for (int i = 0; i < 8; i++)
#pragma unroll
        for (int j = 0; j < 8; j++) acc[i][j] = 0.0f;

#pragma unroll
    for (int d = 0; d < 64; d++) {
        float a[8], qq[8];
#pragma unroll
        for (int i = 0; i < 8; i++) a[i] = Vs[d * 128 + ty * 8 + i];
#pragma unroll
        for (int j = 0; j < 8; j++) qq[j] = Qs[d * 128 + tx * 8 + j];
#pragma unroll
        for (int i = 0; i < 8; i++)
#pragma unroll
            for (int j = 0; j < 8; j++) acc[i][j] += a[i] * qq[j];
    }

    const float g = gamma[0];
    const float* xb = x + ((size_t)b * CH + c0) * NN + n0;
    float* ob = out + ((size_t)b * CH + c0) * NN + n0;
#pragma unroll
    for (int i = 0; i < 8; i++) {
        int cc = ty * 8 + i;
#pragma unroll
        for (int j = 0; j < 8; j++) {
            int n = tx * 8 + j;
            ob[(size_t)cc * NN + n] = xb[(size_t)cc * NN + n] + g * normv[n] * acc[i][j];
        }
    }
}

// ---------------------------------------------------------------------------
extern "C" void kernel_launch(void* const* d_in, const int* in_sizes, int n_in,
                              void* d_out, int out_size)
{
    const float* x     = (const float*)d_in[0];
    const float* wq    = (const float*)d_in[1];
    const float* bq    = (const float*)d_in[2];
    const float* wk    = (const float*)d_in[3];
    const float* bk    = (const float*)d_in[4];
    const float* wv    = (const float*)d_in[5];
    const float* bv    = (const float*)d_in[6];
    const float* gamma = (const float*)d_in[7];
    float* out = (float*)d_out;

    static bool attr_done = false;
    if (!attr_done) {
        cudaFuncSetAttribute(out_kernel, cudaFuncAttributeMaxDynamicSharedMemorySize,
                             (64 * 128 * 2 + 64 + 128) * (int)sizeof(float));
        attr_done = true;
    }

    init_kernel<<<(BATCH * DD * CH + 255) / 256, 256>>>();
    qk_kernel<<<dim3(NN / 128, BATCH), 256>>>(x, wq, bq, wk, bk);
    kxt_kernel<<<dim3(CH / 128, NN / 512, BATCH), 256>>>(x);
    kv_kernel<<<dim3(CH / 128, (BATCH * DD) / 64, 4), 256>>>(wv, bv);
    out_kernel<<<dim3(NN / 128, CH / 128, BATCH), 256,
                 (64 * 128 * 2 + 64 + 128) * sizeof(float)>>>(x, gamma, out);
}

// round 2
// speedup vs baseline: 1.7007x; 1.7007x over previous
#include <cuda_runtime.h>

#define BATCH 8
#define CH    512
#define DD    64
#define NN    4096
#define EPSF  1e-10f

// Scratch (allocation-free rule: __device__ globals)
__device__ float g_Qf[BATCH * DD * NN];    // delu(Q), [b][d][n]
__device__ float g_KXt[BATCH * DD * CH];   // Kf @ x^T, [b][d][c]  (atomic accum)
__device__ float g_KV[BATCH * DD * CH];    // KXt @ wv^T + bias    (atomic accum)
__device__ float g_Ksum[BATCH * DD];       // EPS + sum_n Kf

__device__ __forceinline__ float delu(float v) {
    return 10.0f * fmaxf(v, 0.0f) + __expf(10.0f * fminf(v, 0.0f));
}

// ---------------------------------------------------------------------------
// 0) init: zero accumulators, Ksum = EPS
// ---------------------------------------------------------------------------
__global__ void init_kernel() {
    int i = blockIdx.x * blockDim.x + threadIdx.x;
    if (i < BATCH * DD * CH) { g_KXt[i] = 0.0f; g_KV[i] = 0.0f; }
    if (i < BATCH * DD) g_Ksum[i] = EPSF;
}

// ---------------------------------------------------------------------------
// 1) FUSED: Q/K projection + delu + Ksum + KXt accumulation.
//    Phase 1: [128m x 128n x 512k] GEMM, M rows 0..63 = wq, 64..127 = wk.
//             Double-buffered smem, register-staged global loads.
//             Qf -> gmem, Kf -> smem only.
//    Phase 2: KXt[64m x 512c] += Kf_s[64 x 128n] * x[c x 128n] (8 c-chunks of 64),
//             atomic accumulate into g_KXt.
//    grid = (NN/128, BATCH), 256 threads.
//
// Dynamic smem layout (floats):
//   region1 [0, 8448):   phase1: sA[2][16][132] (0..4224) + sB[2][16][128] (4224..8320)
//                        phase2: Xs[64][132]
//   Kf_s    [8448, 16896): [64][132]
// ---------------------------------------------------------------------------
__global__ __launch_bounds__(256, 2) void qk_kxt_kernel(
    const float* __restrict__ x, const float* __restrict__ wq,
    const float* __restrict__ bq, const float* __restrict__ wk,
    const float* __restrict__ bk)
{
    extern __shared__ float sm[];
    float* sA   = sm;           // [2][16][132]  (k-major rows, m columns)
    float* sB   = sm + 4224;    // [2][16][128]
    float* Kf_s = sm + 8448;    // [64][132]

    const int b  = blockIdx.y;
    const int n0 = blockIdx.x * 128;
    const int t  = threadIdx.x;
    const float* xb = x + (size_t)b * CH * NN;

    // ---- phase 1: projection GEMM ----
    const int tx = t & 15, ty = t >> 4;       // compute map: 8m x 8n micro
    const int aM  = t >> 2;                   // 0..63 (A-load row)
    const int aKG = t & 3;                    // k-group (4 floats)
    const int bKK = t >> 5;                   // 0..7 (B-load k row)
    const int bNF = t & 31;                   // n float4 index

    float acc[8][8];
#pragma unroll
    for (int i = 0; i < 8; i++)
#pragma unroll
        for (int j = 0; j < 8; j++) acc[i][j] = 0.0f;

    float4 ra0, ra1, rb0, rb1;
    // preload k0 = 0
    ra0 = *(const float4*)&wq[(size_t)aM * CH + aKG * 4];
    ra1 = *(const float4*)&wk[(size_t)aM * CH + aKG * 4];
    rb0 = *(const float4*)&xb[(size_t)bKK * NN + n0 + bNF * 4];
    rb1 = *(const float4*)&xb[(size_t)(bKK + 8) * NN + n0 + bNF * 4];
    {
        float* dA = sA + (aKG * 4) * 132;
        dA[0 * 132 + aM] = ra0.x; dA[1 * 132 + aM] = ra0.y;
        dA[2 * 132 + aM] = ra0.z; dA[3 * 132 + aM] = ra0.w;
        dA[0 * 132 + aM + 64] = ra1.x; dA[1 * 132 + aM + 64] = ra1.y;
        dA[2 * 132 + aM + 64] = ra1.z; dA[3 * 132 + aM + 64] = ra1.w;
        *(float4*)&sB[bKK * 128 + bNF * 4] = rb0;
        *(float4*)&sB[(bKK + 8) * 128 + bNF * 4] = rb1;
    }
    __syncthreads();

    int buf = 0;
    for (int kt = 0; kt < 32; kt++) {
        if (kt < 31) {
            const int k0 = (kt + 1) * 16;
            ra0 = *(const float4*)&wq[(size_t)aM * CH + k0 + aKG * 4];
            ra1 = *(const float4*)&wk[(size_t)aM * CH + k0 + aKG * 4];
            rb0 = *(const float4*)&xb[(size_t)(k0 + bKK) * NN + n0 + bNF * 4];
            rb1 = *(const float4*)&xb[(size_t)(k0 + bKK + 8) * NN + n0 + bNF * 4];
        }
        const float* cA = sA + buf * 2112;
        const float* cB = sB + buf * 2048;
#pragma unroll
        for (int kk = 0; kk < 16; kk++) {
            float4 A0 = *(const float4*)&cA[kk * 132 + ty * 8];
            float4 A1 = *(const float4*)&cA[kk * 132 + ty * 8 + 4];
            float4 B0 = *(const float4*)&cB[kk * 128 + tx * 8];
            float4 B1 = *(const float4*)&cB[kk * 128 + tx * 8 + 4];
            float av[8] = {A0.x, A0.y, A0.z, A0.w, A1.x, A1.y, A1.z, A1.w};
            float bv_[8] = {B0.x, B0.y, B0.z, B0.w, B1.x, B1.y, B1.z, B1.w};
#pragma unroll
            for (int i = 0; i < 8; i++)
#pragma unroll
                for (int j = 0; j < 8; j++) acc[i][j] += av[i] * bv_[j];
        }
        if (kt < 31) {
            float* dA = sA + (buf ^ 1) * 2112 + (aKG * 4) * 132;
            dA[0 * 132 + aM] = ra0.x; dA[1 * 132 + aM] = ra0.y;
            dA[2 * 132 + aM] = ra0.z; dA[3 * 132 + aM] = ra0.w;
            dA[0 * 132 + aM + 64] = ra1.x; dA[1 * 132 + aM + 64] = ra1.y;
            dA[2 * 132 + aM + 64] = ra1.z; dA[3 * 132 + aM + 64] = ra1.w;
            float* dB = sB + (buf ^ 1) * 2048;
            *(float4*)&dB[bKK * 128 + bNF * 4] = rb0;
            *(float4*)&dB[(bKK + 8) * 128 + bNF * 4] = rb1;
            __syncthreads();
            buf ^= 1;
        }
    }

    // ---- epilogue: bias + delu; Q -> gmem, K -> smem ----
    if (ty < 8) {
#pragma unroll
        for (int i = 0; i < 8; i++) {
            const int m = ty * 8 + i;
            const float bias = bq[m];
            float4 o0, o1;
            o0.x = delu(acc[i][0] + bias); o0.y = delu(acc[i][1] + bias);
            o0.z = delu(acc[i][2] + bias); o0.w = delu(acc[i][3] + bias);
            o1.x = delu(acc[i][4] + bias); o1.y = delu(acc[i][5] + bias);
            o1.z = delu(acc[i][6] + bias); o1.w = delu(acc[i][7] + bias);
            float* dst = g_Qf + ((size_t)b * DD + m) * NN + n0 + tx * 8;
            *(float4*)dst = o0; *(float4*)(dst + 4) = o1;
        }
    } else {
#pragma unroll
        for (int i = 0; i < 8; i++) {
            const int mk = (ty - 8) * 8 + i;
            const float bias = bk[mk];
            float4 o0, o1;
            o0.x = delu(acc[i][0] + bias); o0.y = delu(acc[i][1] + bias);
            o0.z = delu(acc[i][2] + bias); o0.w = delu(acc[i][3] + bias);
            o1.x = delu(acc[i][4] + bias); o1.y = delu(acc[i][5] + bias);
            o1.z = delu(acc[i][6] + bias); o1.w = delu(acc[i][7] + bias);
            *(float4*)&Kf_s[mk * 132 + tx * 8] = o0;
            *(float4*)&Kf_s[mk * 132 + tx * 8 + 4] = o1;
        }
    }
    __syncthreads();

    // ---- Ksum partials ----
    {
        const int w = t >> 5, lane = t & 31;
#pragma unroll
        for (int r = 0; r < 8; r++) {
            const int m = w * 8 + r;
            float s = Kf_s[m * 132 + lane] + Kf_s[m * 132 + lane + 32]
                    + Kf_s[m * 132 + lane + 64] + Kf_s[m * 132 + lane + 96];
#pragma unroll
            for (int off = 16; off > 0; off >>= 1)
                s += __shfl_down_sync(0xffffffffu, s, off);
            if (lane == 0) atomicAdd(&g_Ksum[b * DD + m], s);
        }
    }

    // ---- phase 2: KXt += Kf_s @ x^T, 8 chunks of 64 c ----
    const int p_lane = t & 31, p_w = t >> 5;   // c = p_lane & p_lane+32, m = p_w*8+i
    for (int c0 = 0; c0 < CH; c0 += 64) {
        __syncthreads();   // prev chunk readers done before overwriting Xs
#pragma unroll
        for (int r = 0; r < 8; r++) {
            const int id = t + r * 256;
            const int c = id >> 5, nf = id & 31;
            *(float4*)&sm[c * 132 + nf * 4] =
                *(const float4*)&xb[(size_t)(c0 + c) * NN + n0 + nf * 4];
        }
        __syncthreads();

        float accP[8][2];
#pragma unroll
        for (int i = 0; i < 8; i++) { accP[i][0] = 0.0f; accP[i][1] = 0.0f; }

#pragma unroll 4
        for (int n4 = 0; n4 < 128; n4 += 4) {
            float4 X0 = *(const float4*)&sm[p_lane * 132 + n4];
            float4 X1 = *(const float4*)&sm[(p_lane + 32) * 132 + n4];
#pragma unroll
            for (int i = 0; i < 8; i++) {
                float4 K4 = *(const float4*)&Kf_s[(p_w * 8 + i) * 132 + n4];
                accP[i][0] += K4.x * X0.x; accP[i][0] += K4.y * X0.y;
                accP[i][0] += K4.z * X0.z; accP[i][0] += K4.w * X0.w;
                accP[i][1] += K4.x * X1.x; accP[i][1] += K4.y * X1.y;
                accP[i][1] += K4.z * X1.z; accP[i][1] += K4.w * X1.w;
            }
        }
#pragma unroll
        for (int i = 0; i < 8; i++) {
            const int m = p_w * 8 + i;
            atomicAdd(&g_KXt[((size_t)b * DD + m) * CH + c0 + p_lane], accP[i][0]);
            atomicAdd(&g_KXt[((size_t)b * DD + m) * CH + c0 + p_lane + 32], accP[i][1]);
        }
    }
}

// ---------------------------------------------------------------------------
// 2) KV = KXt_flat[512,512] @ wv^T + (Ksum-EPS)*bv.  K split into 4 chunks.
//    grid = (CH/128, 8, 4), 256 threads, 64x128 tile.
// ---------------------------------------------------------------------------
__global__ __launch_bounds__(256) void kv_kernel(
    const float* __restrict__ wv, const float* __restrict__ bv)
{
    __shared__ float As[32][65];
    __shared__ float Bs[32][129];
    const int e0 = blockIdx.x * 128;
    const int m0 = blockIdx.y * 64;      // global row in [0, B*DD)
    const int c0 = blockIdx.z * 128;     // K-split chunk
    const int t  = threadIdx.x;
    const int tx = t & 31, ty = t >> 5;

    float acc[8][4];
#pragma unroll
    for (int i = 0; i < 8; i++)
#pragma unroll
        for (int j = 0; j < 4; j++) acc[i][j] = 0.0f;

    for (int k0 = c0; k0 < c0 + 128; k0 += 32) {
#pragma unroll
        for (int r = 0; r < 8; r++) {
            int idx = t + r * 256;
            int m = idx >> 5, kk = idx & 31;
            As[kk][m] = g_KXt[(size_t)(m0 + m) * CH + k0 + kk];
        }
#pragma unroll
        for (int r = 0; r < 16; r++) {
            int idx = t + r * 256;
            int e = idx >> 5, kk = idx & 31;
            Bs[kk][e] = wv[(size_t)(e0 + e) * CH + k0 + kk];
        }
        __syncthreads();
#pragma unroll
        for (int kk = 0; kk < 32; kk++) {
            float a[8], bb[4];
#pragma unroll
            for (int i = 0; i < 8; i++) a[i] = As[kk][ty * 8 + i];
#pragma unroll
            for (int j = 0; j < 4; j++) bb[j] = Bs[kk][tx * 4 + j];
#pragma unroll
            for (int i = 0; i < 8; i++)
#pragma unroll
                for (int j = 0; j < 4; j++) acc[i][j] += a[i] * bb[j];
        }
        __syncthreads();
    }

#pragma unroll
    for (int i = 0; i < 8; i++) {
        int m = m0 + ty * 8 + i;
#pragma unroll
        for (int j = 0; j < 4; j++) {
            int e = e0 + tx * 4 + j;
            float v = acc[i][j];
            if (blockIdx.z == 0) v += (g_Ksum[m] - EPSF) * bv[e];
            atomicAdd(&g_KV[(size_t)m * CH + e], v);
        }
    }
}

// ---------------------------------------------------------------------------
// 3) out = x + gamma * norm[n] * (Qf^T @ KV).  K = 64, all float4 paths.
//    grid = (NN/128, CH/128, BATCH), 256 threads, dynamic smem.
// ---------------------------------------------------------------------------
__global__ __launch_bounds__(256, 2) void out_kernel(
    const float* __restrict__ x, const float* __restrict__ gamma,
    float* __restrict__ out)
{
    extern __shared__ float sm[];
    float* Qs    = sm;             // [64][128]  Qf tile (d x n)
    float* Vs    = sm + 8192;      // [64][128]  KV tile (d x c)
    float* Ks    = sm + 16384;     // [64]
    float* normv = sm + 16448;     // [128]

    const int b  = blockIdx.z;
    const int c0 = blockIdx.y * 128;
    const int n0 = blockIdx.x * 128;
    const int t  = threadIdx.x;
    const float* qf = g_Qf + (size_t)b * DD * NN;
    const float* kv = g_KV + (size_t)b * DD * CH;

#pragma unroll
    for (int r = 0; r < 8; r++) {
        const int id = t + r * 256;
        const int d = id >> 5, nf = id & 31;
        *(float4*)&Qs[d * 128 + nf * 4] = *(const float4*)&qf[(size_t)d * NN + n0 + nf * 4];
        *(float4*)&Vs[d * 128 + nf * 4] = *(const float4*)&kv[(size_t)d * CH + c0 + nf * 4];
    }
    if (t < 64) Ks[t] = g_Ksum[b * DD + t];
    __syncthreads();

    if (t < 128) {
        float s = 0.0f;
#pragma unroll
        for (int d = 0; d < 64; d++) s += Qs[d * 128 + t] * Ks[d];
        normv[t] = 1.0f / s;
    }
    __syncthreads();

    const int tx = t & 15, ty = t >> 4;   // ty -> 8 c rows, tx -> 8 n cols
    float acc[8][8];
#pragma unroll
    for (int i = 0; i < 8; i++)
#pragma unroll
        for (int j = 0; j < 8; j++) acc[i][j] = 0.0f;

#pragma unroll 4
    for (int d = 0; d < 64; d++) {
        float4 V0 = *(const float4*)&Vs[d * 128 + ty * 8];
        float4 V1 = *(const float4*)&Vs[d * 128 + ty * 8 + 4];
        float4 Q0 = *(const float4*)&Qs[d * 128 + tx * 8];
        float4 Q1 = *(const float4*)&Qs[d * 128 + tx * 8 + 4];
        float av[8] = {V0.x, V0.y, V0.z, V0.w, V1.x, V1.y, V1.z, V1.w};
        float qv[8] = {Q0.x, Q0.y, Q0.z, Q0.w, Q1.x, Q1.y, Q1.z, Q1.w};
#pragma unroll
        for (int i = 0; i < 8; i++)
#pragma unroll
            for (int j = 0; j < 8; j++) acc[i][j] += av[i] * qv[j];
    }

    const float g = gamma[0];
    float4 nv0 = *(const float4*)&normv[tx * 8];
    float4 nv1 = *(const float4*)&normv[tx * 8 + 4];
    const float nvv[8] = {nv0.x, nv0.y, nv0.z, nv0.w, nv1.x, nv1.y, nv1.z, nv1.w};
    const float* xb = x + ((size_t)b * CH + c0) * NN + n0;
    float* ob = out + ((size_t)b * CH + c0) * NN + n0;
#pragma unroll
    for (int i = 0; i < 8; i++) {
        const int cc = ty * 8 + i;
        const float* xr = xb + (size_t)cc * NN + tx * 8;
        float* orow = ob + (size_t)cc * NN + tx * 8;
        float4 x0 = *(const float4*)xr;
        float4 x1 = *(const float4*)(xr + 4);
        float4 o0, o1;
        o0.x = x0.x + g * nvv[0] * acc[i][0];
        o0.y = x0.y + g * nvv[1] * acc[i][1];
        o0.z = x0.z + g * nvv[2] * acc[i][2];
        o0.w = x0.w + g * nvv[3] * acc[i][3];
        o1.x = x1.x + g * nvv[4] * acc[i][4];
        o1.y = x1.y + g * nvv[5] * acc[i][5];
        o1.z = x1.z + g * nvv[6] * acc[i][6];
        o1.w = x1.w + g * nvv[7] * acc[i][7];
        *(float4*)orow = o0;
        *(float4*)(orow + 4) = o1;
    }
}

// ---------------------------------------------------------------------------
extern "C" void kernel_launch(void* const* d_in, const int* in_sizes, int n_in,
                              void* d_out, int out_size)
{
    const float* x     = (const float*)d_in[0];
    const float* wq    = (const float*)d_in[1];
    const float* bq    = (const float*)d_in[2];
    const float* wk    = (const float*)d_in[3];
    const float* bk    = (const float*)d_in[4];
    const float* wv    = (const float*)d_in[5];
    const float* bv    = (const float*)d_in[6];
    const float* gamma = (const float*)d_in[7];
    float* out = (float*)d_out;

    static bool attr_done = false;
    if (!attr_done) {
        cudaFuncSetAttribute(qk_kxt_kernel, cudaFuncAttributeMaxDynamicSharedMemorySize,
                             16896 * (int)sizeof(float));
        cudaFuncSetAttribute(out_kernel, cudaFuncAttributeMaxDynamicSharedMemorySize,
                             16576 * (int)sizeof(float));
        attr_done = true;
    }

    init_kernel<<<(BATCH * DD * CH + 255) / 256, 256>>>();
    qk_kxt_kernel<<<dim3(NN / 128, BATCH), 256, 16896 * sizeof(float)>>>(x, wq, bq, wk, bk);
    kv_kernel<<<dim3(CH / 128, (BATCH * DD) / 64, 4), 256>>>(wv, bv);
    out_kernel<<<dim3(NN / 128, CH / 128, BATCH), 256, 16576 * sizeof(float)>>>(x, gamma, out);
}

// round 3
// speedup vs baseline: 1.7850x; 1.0496x over previous
#include <cuda_runtime.h>
#include <cstdint>

#define BATCH 8
#define CH    512
#define DD    64
#define NN    4096
#define EPSF  1e-10f

typedef unsigned long long ull;

// Scratch (allocation-free rule: __device__ globals)
__device__ float g_Wt[CH * 128];           // transposed stacked wq/wk: [k][m]
__device__ float g_Qf[BATCH * DD * NN];    // delu(Q), [b][d][n]
__device__ float g_KXt[BATCH * DD * CH];   // Kf @ x^T (atomic accum)
__device__ float g_KV[BATCH * DD * CH];    // KXt @ wv^T + bias (atomic accum)
__device__ float g_Ksum[BATCH * DD];       // EPS + sum_n Kf

__device__ __forceinline__ float delu(float v) {
    return 10.0f * fmaxf(v, 0.0f) + __expf(10.0f * fminf(v, 0.0f));
}

// ---- packed f32x2 helpers ----
__device__ __forceinline__ void fma2(ull& d, ull a, ull b) {
    asm("fma.rn.f32x2 %0, %1, %2, %0;" : "+l"(d) : "l"(a), "l"(b));
}
__device__ __forceinline__ ull dup2(float f) {
    ull r; unsigned u = __float_as_uint(f);
    asm("mov.b64 %0, {%1, %2};" : "=l"(r) : "r"(u), "r"(u));
    return r;
}
__device__ __forceinline__ float2 unpk(ull v) {
    unsigned lo, hi;
    asm("mov.b64 {%0, %1}, %2;" : "=r"(lo), "=r"(hi) : "l"(v));
    return make_float2(__uint_as_float(lo), __uint_as_float(hi));
}
__device__ __forceinline__ ull d2u(double d) { return (ull)__double_as_longlong(d); }

__device__ __forceinline__ void cpa16(uint32_t dst, const void* src) {
    asm volatile("cp.async.cg.shared.global [%0], [%1], 16;" :: "r"(dst), "l"(src));
}
__device__ __forceinline__ void cp_commit() {
    asm volatile("cp.async.commit_group;" ::: "memory");
}
__device__ __forceinline__ void cp_wait0() {
    asm volatile("cp.async.wait_group 0;" ::: "memory");
}
__device__ __forceinline__ uint32_t sm_u32(const void* p) {
    return (uint32_t)__cvta_generic_to_shared(p);
}

// ---------------------------------------------------------------------------
// 0) init: zero accumulators, Ksum = EPS, build transposed weight panel
// ---------------------------------------------------------------------------
__global__ void init_kernel(const float* __restrict__ wq, const float* __restrict__ wk) {
    int i = blockIdx.x * blockDim.x + threadIdx.x;
    if (i < BATCH * DD * CH) { g_KXt[i] = 0.0f; g_KV[i] = 0.0f; }
    if (i < BATCH * DD) g_Ksum[i] = EPSF;
    if (i < CH * 128) {
        int k = i >> 7, m = i & 127;
        g_Wt[i] = (m < 64) ? wq[(size_t)m * CH + k] : wk[(size_t)(m - 64) * CH + k];
    }
}

// ---------------------------------------------------------------------------
// 1) FUSED: Q/K projection (f32x2 + cp.async) + delu + Ksum + KXt.
//    grid = (NN/128, BATCH), 256 threads.
//    smem floats (25344 total = 101376 B):
//      phase1: sA[2][16][128] @0, sB[2][16][128] @4096
//      phase2: Xs[128][132]   @0
//      Kf_s  : [64][132]      @16896
// ---------------------------------------------------------------------------
__global__ __launch_bounds__(256, 2) void qk_kxt_kernel(
    const float* __restrict__ x,
    const float* __restrict__ bq, const float* __restrict__ bk)
{
    extern __shared__ float sm[];
    float* Kf_s = sm + 16896;

    const int b  = blockIdx.y;
    const int n0 = blockIdx.x * 128;
    const int t  = threadIdx.x;
    const float* xb = x + (size_t)b * CH * NN;

    // ---- phase 1: projection GEMM, f32x2 micro 8m x 8n ----
    const int tx = t & 15, ty = t >> 4;
    const uint32_t sA_u = sm_u32(sm);
    const uint32_t sB_u = sm_u32(sm + 4096);
    const int lkk0 = t >> 5, lf0 = t & 31;          // loader: idx t  -> kk, float4
    const int lkk1 = (t + 256) >> 5, lf1 = t & 31;  // loader: idx t+256

    ull acc2[8][4];
#pragma unroll
    for (int i = 0; i < 8; i++)
#pragma unroll
        for (int j = 0; j < 4; j++) acc2[i][j] = 0ull;

    // prologue: stage 0
    {
        const int k0 = 0;
        cpa16(sA_u + (uint32_t)(lkk0 * 128 + lf0 * 4) * 4, g_Wt + (size_t)(k0 + lkk0) * 128 + lf0 * 4);
        cpa16(sA_u + (uint32_t)(lkk1 * 128 + lf1 * 4) * 4, g_Wt + (size_t)(k0 + lkk1) * 128 + lf1 * 4);
        cpa16(sB_u + (uint32_t)(lkk0 * 128 + lf0 * 4) * 4, xb + (size_t)(k0 + lkk0) * NN + n0 + lf0 * 4);
        cpa16(sB_u + (uint32_t)(lkk1 * 128 + lf1 * 4) * 4, xb + (size_t)(k0 + lkk1) * NN + n0 + lf1 * 4);
        cp_commit();
    }

    int buf = 0;
    for (int kt = 0; kt < 32; kt++) {
        cp_wait0();
        __syncthreads();
        if (kt < 31) {
            const int k0 = (kt + 1) * 16;
            const uint32_t off = (uint32_t)((buf ^ 1) * 2048) * 4;
            cpa16(sA_u + off + (uint32_t)(lkk0 * 128 + lf0 * 4) * 4, g_Wt + (size_t)(k0 + lkk0) * 128 + lf0 * 4);
            cpa16(sA_u + off + (uint32_t)(lkk1 * 128 + lf1 * 4) * 4, g_Wt + (size_t)(k0 + lkk1) * 128 + lf1 * 4);
            cpa16(sB_u + off + (uint32_t)(lkk0 * 128 + lf0 * 4) * 4, xb + (size_t)(k0 + lkk0) * NN + n0 + lf0 * 4);
            cpa16(sB_u + off + (uint32_t)(lkk1 * 128 + lf1 * 4) * 4, xb + (size_t)(k0 + lkk1) * NN + n0 + lf1 * 4);
            cp_commit();
        }
        const float* cA = sm + buf * 2048;
        const float* cB = sm + 4096 + buf * 2048;
#pragma unroll
        for (int kk = 0; kk < 16; kk++) {
            float4 A0 = *(const float4*)&cA[kk * 128 + ty * 8];
            float4 A1 = *(const float4*)&cA[kk * 128 + ty * 8 + 4];
            double2 Bq0 = *(const double2*)&cB[kk * 128 + tx * 8];
            double2 Bq1 = *(const double2*)&cB[kk * 128 + tx * 8 + 4];
            ull b2[4] = {d2u(Bq0.x), d2u(Bq0.y), d2u(Bq1.x), d2u(Bq1.y)};
            ull ad[8] = {dup2(A0.x), dup2(A0.y), dup2(A0.z), dup2(A0.w),
                         dup2(A1.x), dup2(A1.y), dup2(A1.z), dup2(A1.w)};
#pragma unroll
            for (int i = 0; i < 8; i++)
#pragma unroll
                for (int j = 0; j < 4; j++) fma2(acc2[i][j], ad[i], b2[j]);
        }
        buf ^= 1;
    }

    // ---- epilogue: bias + delu; Q -> gmem, K -> smem ----
    {
#pragma unroll
        for (int i = 0; i < 8; i++) {
            const int m = ty * 8 + i;
            float v[8];
#pragma unroll
            for (int j = 0; j < 4; j++) {
                float2 p = unpk(acc2[i][j]);
                v[2 * j] = p.x; v[2 * j + 1] = p.y;
            }
            if (ty < 8) {
                const float bias = bq[m];
                float4 o0, o1;
                o0.x = delu(v[0] + bias); o0.y = delu(v[1] + bias);
                o0.z = delu(v[2] + bias); o0.w = delu(v[3] + bias);
                o1.x = delu(v[4] + bias); o1.y = delu(v[5] + bias);
                o1.z = delu(v[6] + bias); o1.w = delu(v[7] + bias);
                float* dst = g_Qf + ((size_t)b * DD + m) * NN + n0 + tx * 8;
                *(float4*)dst = o0; *(float4*)(dst + 4) = o1;
            } else {
                const int mk = m - 64;
                const float bias = bk[mk];
                float4 o0, o1;
                o0.x = delu(v[0] + bias); o0.y = delu(v[1] + bias);
                o0.z = delu(v[2] + bias); o0.w = delu(v[3] + bias);
                o1.x = delu(v[4] + bias); o1.y = delu(v[5] + bias);
                o1.z = delu(v[6] + bias); o1.w = delu(v[7] + bias);
                *(float4*)&Kf_s[mk * 132 + tx * 8] = o0;
                *(float4*)&Kf_s[mk * 132 + tx * 8 + 4] = o1;
            }
        }
    }
    __syncthreads();

    // ---- Ksum partials ----
    {
        const int w = t >> 5, lane = t & 31;
#pragma unroll
        for (int r = 0; r < 8; r++) {
            const int m = w * 8 + r;
            float s = Kf_s[m * 132 + lane] + Kf_s[m * 132 + lane + 32]
                    + Kf_s[m * 132 + lane + 64] + Kf_s[m * 132 + lane + 96];
#pragma unroll
            for (int off = 16; off > 0; off >>= 1)
                s += __shfl_down_sync(0xffffffffu, s, off);
            if (lane == 0) atomicAdd(&g_Ksum[b * DD + m], s);
        }
    }

    // ---- phase 2: KXt += Kf_s @ x^T, 4 c-chunks of 128, micro 8m x 4c ----
    const int txc = t & 31, tym = t >> 5;
    for (int c0 = 0; c0 < CH; c0 += 128) {
        __syncthreads();
#pragma unroll
        for (int r = 0; r < 16; r++) {
            const int id = t + r * 256;
            const int c = id >> 5, nf = id & 31;
            *(float4*)&sm[c * 132 + nf * 4] =
                *(const float4*)&xb[(size_t)(c0 + c) * NN + n0 + nf * 4];
        }
        __syncthreads();

        float accP[8][4];
#pragma unroll
        for (int i = 0; i < 8; i++)
#pragma unroll
            for (int j = 0; j < 4; j++) accP[i][j] = 0.0f;

#pragma unroll 4
        for (int n4 = 0; n4 < 128; n4 += 4) {
            float4 X[4];
#pragma unroll
            for (int j = 0; j < 4; j++)
                X[j] = *(const float4*)&sm[(txc + 32 * j) * 132 + n4];
#pragma unroll
            for (int i = 0; i < 8; i++) {
                float4 K4 = *(const float4*)&Kf_s[(tym * 8 + i) * 132 + n4];
#pragma unroll
                for (int j = 0; j < 4; j++) {
                    accP[i][j] += K4.x * X[j].x;
                    accP[i][j] += K4.y * X[j].y;
                    accP[i][j] += K4.z * X[j].z;
                    accP[i][j] += K4.w * X[j].w;
                }
            }
        }
#pragma unroll
        for (int i = 0; i < 8; i++) {
            const int m = tym * 8 + i;
#pragma unroll
            for (int j = 0; j < 4; j++)
                atomicAdd(&g_KXt[((size_t)b * DD + m) * CH + c0 + txc + 32 * j], accP[i][j]);
        }
    }
}

// ---------------------------------------------------------------------------
// 2) KV = KXt_flat[512,512] @ wv^T + (Ksum-EPS)*bv.  K split into 16 chunks.
//    grid = (CH/128, 8, 16), 256 threads, 64x128 tile.
// ---------------------------------------------------------------------------
__global__ __launch_bounds__(256) void kv_kernel(
    const float* __restrict__ wv, const float* __restrict__ bv)
{
    __shared__ float As[32][65];
    __shared__ float Bs[32][129];
    const int e0 = blockIdx.x * 128;
    const int m0 = blockIdx.y * 64;
    const int c0 = blockIdx.z * 32;
    const int t  = threadIdx.x;
    const int tx = t & 31, ty = t >> 5;

    float acc[8][4];
#pragma unroll
    for (int i = 0; i < 8; i++)
#pragma unroll
        for (int j = 0; j < 4; j++) acc[i][j] = 0.0f;

    {
        const int k0 = c0;
#pragma unroll
        for (int r = 0; r < 8; r++) {
            int idx = t + r * 256;
            int m = idx >> 5, kk = idx & 31;
            As[kk][m] = g_KXt[(size_t)(m0 + m) * CH + k0 + kk];
        }
#pragma unroll
        for (int r = 0; r < 16; r++) {
            int idx = t + r * 256;
            int e = idx >> 5, kk = idx & 31;
            Bs[kk][e] = wv[(size_t)(e0 + e) * CH + k0 + kk];
        }
        __syncthreads();
#pragma unroll
        for (int kk = 0; kk < 32; kk++) {
            float a[8], bb[4];
#pragma unroll
            for (int i = 0; i < 8; i++) a[i] = As[kk][ty * 8 + i];
#pragma unroll
            for (int j = 0; j < 4; j++) bb[j] = Bs[kk][tx * 4 + j];
#pragma unroll
            for (int i = 0; i < 8; i++)
#pragma unroll
                for (int j = 0; j < 4; j++) acc[i][j] += a[i] * bb[j];
        }
    }

#pragma unroll
    for (int i = 0; i < 8; i++) {
        int m = m0 + ty * 8 + i;
#pragma unroll
        for (int j = 0; j < 4; j++) {
            int e = e0 + tx * 4 + j;
            float v = acc[i][j];
            if (blockIdx.z == 0) v += (g_Ksum[m] - EPSF) * bv[e];
            atomicAdd(&g_KV[(size_t)m * CH + e], v);
        }
    }
}

// ---------------------------------------------------------------------------
// 3) out = x + gamma * norm[n] * (Qf^T @ KV).  f32x2, tile c128 x n256, K=64.
//    grid = (NN/256, CH/128, BATCH), 512 threads.
//    smem (25408 floats = 101632 B): Qs[64][260] @0, Vs[64][132] @16640,
//    Ks[64] @25088, normv[256] @25152.
// ---------------------------------------------------------------------------
__global__ __launch_bounds__(512) void out_kernel(
    const float* __restrict__ x, const float* __restrict__ gamma,
    float* __restrict__ out)
{
    extern __shared__ float sm[];
    float* Qs    = sm;
    float* Vs    = sm + 16640;
    float* Ks    = sm + 25088;
    float* normv = sm + 25152;

    const int b  = blockIdx.z;
    const int c0 = blockIdx.y * 128;
    const int n0 = blockIdx.x * 256;
    const int t  = threadIdx.x;
    const float* qf = g_Qf + (size_t)b * DD * NN;
    const float* kv = g_KV + (size_t)b * DD * CH;

#pragma unroll
    for (int r = 0; r < 8; r++) {
        const int id = t + r * 512;
        const int d = id >> 6, nf = id & 63;
        *(float4*)&Qs[d * 260 + nf * 4] = *(const float4*)&qf[(size_t)d * NN + n0 + nf * 4];
    }
#pragma unroll
    for (int r = 0; r < 4; r++) {
        const int id = t + r * 512;
        const int d = id >> 5, cf = id & 31;
        *(float4*)&Vs[d * 132 + cf * 4] = *(const float4*)&kv[(size_t)d * CH + c0 + cf * 4];
    }
    if (t < 64) Ks[t] = g_Ksum[b * DD + t];
    __syncthreads();

    if (t < 256) {
        float s = 0.0f;
#pragma unroll
        for (int d = 0; d < 64; d++) s += Qs[d * 260 + t] * Ks[d];
        normv[t] = 1.0f / s;
    }
    __syncthreads();

    const int tx = t & 31, tyc = t >> 5;   // tyc 0..15 -> 8 c rows each
    ull acc2[8][4];
#pragma unroll
    for (int i = 0; i < 8; i++)
#pragma unroll
        for (int j = 0; j < 4; j++) acc2[i][j] = 0ull;

#pragma unroll 4
    for (int d = 0; d < 64; d++) {
        double2 Qa = *(const double2*)&Qs[d * 260 + tx * 4];
        double2 Qb = *(const double2*)&Qs[d * 260 + tx * 4 + 128];
        float4 V0 = *(const float4*)&Vs[d * 132 + tyc * 8];
        float4 V1 = *(const float4*)&Vs[d * 132 + tyc * 8 + 4];
        ull qa0 = d2u(Qa.x), qa1 = d2u(Qa.y), qb0 = d2u(Qb.x), qb1 = d2u(Qb.y);
        float vv[8] = {V0.x, V0.y, V0.z, V0.w, V1.x, V1.y, V1.z, V1.w};
#pragma unroll
        for (int i = 0; i < 8; i++) {
            ull vd = dup2(vv[i]);
            fma2(acc2[i][0], vd, qa0);
            fma2(acc2[i][1], vd, qa1);
            fma2(acc2[i][2], vd, qb0);
            fma2(acc2[i][3], vd, qb1);
        }
    }

    const float g = gamma[0];
    float4 nva = *(const float4*)&normv[tx * 4];
    float4 nvb = *(const float4*)&normv[tx * 4 + 128];
#pragma unroll
    for (int i = 0; i < 8; i++) {
        const int cc = c0 + tyc * 8 + i;
        const size_t base = ((size_t)b * CH + cc) * NN + n0;
        float2 p0 = unpk(acc2[i][0]), p1 = unpk(acc2[i][1]);
        float2 p2 = unpk(acc2[i][2]), p3 = unpk(acc2[i][3]);
        float4 xa = *(const float4*)&x[base + tx * 4];
        float4 xb2 = *(const float4*)&x[base + tx * 4 + 128];
        float4 oa, ob;
        oa.x = xa.x + g * nva.x * p0.x;
        oa.y = xa.y + g * nva.y * p0.y;
        oa.z = xa.z + g * nva.z * p1.x;
        oa.w = xa.w + g * nva.w * p1.y;
        ob.x = xb2.x + g * nvb.x * p2.x;
        ob.y = xb2.y + g * nvb.y * p2.y;
        ob.z = xb2.z + g * nvb.z * p3.x;
        ob.w = xb2.w + g * nvb.w * p3.y;
        *(float4*)&out[base + tx * 4] = oa;
        *(float4*)&out[base + tx * 4 + 128] = ob;
    }
}

// ---------------------------------------------------------------------------
extern "C" void kernel_launch(void* const* d_in, const int* in_sizes, int n_in,
                              void* d_out, int out_size)
{
    const float* x     = (const float*)d_in[0];
    const float* wq    = (const float*)d_in[1];
    const float* bq    = (const float*)d_in[2];
    const float* wk    = (const float*)d_in[3];
    const float* bk    = (const float*)d_in[4];
    const float* wv    = (const float*)d_in[5];
    const float* bv    = (const float*)d_in[6];
    const float* gamma = (const float*)d_in[7];
    float* out = (float*)d_out;

    static bool attr_done = false;
    if (!attr_done) {
        cudaFuncSetAttribute(qk_kxt_kernel, cudaFuncAttributeMaxDynamicSharedMemorySize,
                             25344 * (int)sizeof(float));
        cudaFuncSetAttribute(out_kernel, cudaFuncAttributeMaxDynamicSharedMemorySize,
                             25408 * (int)sizeof(float));
        attr_done = true;
    }

    init_kernel<<<(BATCH * DD * CH + 255) / 256, 256>>>(wq, wk);
    qk_kxt_kernel<<<dim3(NN / 128, BATCH), 256, 25344 * sizeof(float)>>>(x, bq, bk);
    kv_kernel<<<dim3(CH / 128, (BATCH * DD) / 64, 16), 256>>>(wv, bv);
    out_kernel<<<dim3(NN / 256, CH / 128, BATCH), 512, 25408 * sizeof(float)>>>(x, gamma, out);
}

// round 5
// speedup vs baseline: 2.0414x; 1.1436x over previous
#include <cuda_runtime.h>
#include <cuda_bf16.h>
#include <cstdint>

#define BATCH 8
#define CH    512
#define DD    64
#define NN    4096
#define EPSF  1e-10f

typedef unsigned long long ull;

// ---------------- scratch (__device__ globals; no allocs allowed) ----------
__device__ __align__(16) __nv_bfloat16 g_Wh[128 * CH];   // stacked wq/wk hi, [m][k] row-major
__device__ __align__(16) __nv_bfloat16 g_Wl[128 * CH];   // lo residual
__device__ float g_Qf[BATCH * DD * NN];    // delu(Q), [b][d][n]
__device__ float g_KXt[BATCH * DD * CH];   // Kf @ x^T (atomic accum)
__device__ float g_KV[BATCH * DD * CH];    // KXt @ wv^T + bias (atomic accum)
__device__ float g_Ksum[BATCH * DD];       // EPS + sum_n Kf

__device__ __forceinline__ float delu(float v) {
    return 10.0f * fmaxf(v, 0.0f) + __expf(10.0f * fminf(v, 0.0f));
}

// ---------------- f32x2 helpers (out_kernel) ----------
__device__ __forceinline__ void fma2(ull& d, ull a, ull b) {
    asm("fma.rn.f32x2 %0, %1, %2, %0;" : "+l"(d) : "l"(a), "l"(b));
}
__device__ __forceinline__ ull dup2(float f) {
    ull r; unsigned u = __float_as_uint(f);
    asm("mov.b64 %0, {%1, %2};" : "=l"(r) : "r"(u), "r"(u));
    return r;
}
__device__ __forceinline__ float2 unpk(ull v) {
    unsigned lo, hi;
    asm("mov.b64 {%0, %1}, %2;" : "=r"(lo), "=r"(hi) : "l"(v));
    return make_float2(__uint_as_float(lo), __uint_as_float(hi));
}
__device__ __forceinline__ ull d2u(double d) { return (ull)__double_as_longlong(d); }

// ---------------- cp.async ----------
__device__ __forceinline__ void cpa16(uint32_t dst, const void* src) {
    asm volatile("cp.async.cg.shared.global [%0], [%1], 16;" :: "r"(dst), "l"(src));
}
__device__ __forceinline__ void cp_commit() { asm volatile("cp.async.commit_group;" ::: "memory"); }
__device__ __forceinline__ void cp_wait0()  { asm volatile("cp.async.wait_group 0;" ::: "memory"); }
__device__ __forceinline__ uint32_t sm_u32(const void* p) {
    return (uint32_t)__cvta_generic_to_shared(p);
}

// ---------------- mma.sync bf16 helpers ----------
__device__ __forceinline__ void ldsm4(uint32_t& r0, uint32_t& r1, uint32_t& r2, uint32_t& r3,
                                      uint32_t addr) {
    asm volatile("ldmatrix.sync.aligned.m8n8.x4.shared.b16 {%0,%1,%2,%3}, [%4];"
                 : "=r"(r0), "=r"(r1), "=r"(r2), "=r"(r3) : "r"(addr));
}
__device__ __forceinline__ void mma16816(float* c, uint32_t a0, uint32_t a1, uint32_t a2,
                                         uint32_t a3, uint32_t b0, uint32_t b1) {
    asm volatile("mma.sync.aligned.m16n8k16.row.col.f32.bf16.bf16.f32 "
                 "{%0,%1,%2,%3},{%4,%5,%6,%7},{%8,%9},{%0,%1,%2,%3};"
                 : "+f"(c[0]), "+f"(c[1]), "+f"(c[2]), "+f"(c[3])
                 : "r"(a0), "r"(a1), "r"(a2), "r"(a3), "r"(b0), "r"(b1));
}

// smem byte offsets (qk_kxt kernel). Pitch 136 halves (272 B) for mma tiles.
#define XS_OFF   0         // staging x [128k][132n] float = 67584 B ; phase2 Xs; Kf_s region below
#define AH_OFF   67584     // Ah [128m][136k] bf16 = 34816 B   (Kf_s [64][132] floats reuses this)
#define AL_OFF   102400
#define BH_OFF   137216    // Bh [128n][136k] bf16
#define BL_OFF   172032
#define SMEM_TOT 206848

// ---------------------------------------------------------------------------
// 0) init: zero accumulators, Ksum = EPS, split W into bf16 hi/lo panels
// ---------------------------------------------------------------------------
__global__ void init_kernel(const float* __restrict__ wq, const float* __restrict__ wk) {
    int i = blockIdx.x * blockDim.x + threadIdx.x;
    if (i < BATCH * DD * CH) { g_KXt[i] = 0.0f; g_KV[i] = 0.0f; }
    if (i < BATCH * DD) g_Ksum[i] = EPSF;
    if (i < 128 * CH) {
        int m = i >> 9, k = i & 511;
        float w = (m < 64) ? wq[(size_t)m * CH + k] : wk[(size_t)(m - 64) * CH + k];
        __nv_bfloat16 h = __float2bfloat16_rn(w);
        __nv_bfloat16 l = __float2bfloat16_rn(w - __bfloat162float(h));
        g_Wh[i] = h;
        g_Wl[i] = l;
    }
}

// ---------------------------------------------------------------------------
// 1) FUSED: Q/K projection via mma.sync bf16-split + delu + Ksum + KXt (FFMA).
//    grid = (NN/128, BATCH), 256 threads, 1 CTA/SM (202 KB smem).
// ---------------------------------------------------------------------------
__global__ __launch_bounds__(256, 1) void qk_kxt_kernel(
    const float* __restrict__ x,
    const float* __restrict__ bq, const float* __restrict__ bk)
{
    extern __shared__ float sm[];
    const uint32_t smb = sm_u32(sm);
    const int b  = blockIdx.y;
    const int n0 = blockIdx.x * 128;
    const int t  = threadIdx.x;
    const int wid = t >> 5, lane = t & 31;
    const float* xb = x + (size_t)b * CH * NN;

    // warp tile: wm in {0,1} (64 m rows), wn in {0..3} (32 n cols)
    const int wm = wid & 1, wn = wid >> 1;
    const int g  = lane >> 2, tq = lane & 3;

    float acc[4][4][4];
#pragma unroll
    for (int i = 0; i < 4; i++)
#pragma unroll
        for (int j = 0; j < 4; j++)
#pragma unroll
            for (int e = 0; e < 4; e++) acc[i][j][e] = 0.0f;

    // ---- prologue: stage chunk 0 (x float tile + A panels) ----
#pragma unroll
    for (int r = 0; r < 16; r++) {
        int id = t + r * 256;
        int row = id >> 5, f4 = id & 31;
        cpa16(smb + XS_OFF + (uint32_t)(row * 132 + f4 * 4) * 4,
              xb + (size_t)row * NN + n0 + f4 * 4);
    }
#pragma unroll
    for (int r = 0; r < 8; r++) {
        int id = t + r * 256;
        int row = id >> 4, seg = id & 15;
        cpa16(smb + AH_OFF + (uint32_t)(row * 136 + seg * 8) * 2, g_Wh + row * CH + seg * 8);
        cpa16(smb + AL_OFF + (uint32_t)(row * 136 + seg * 8) * 2, g_Wl + row * CH + seg * 8);
    }
    cp_commit();

    const int cn    = t & 127;     // conversion: n index
    const int chalf = t >> 7;      // 0/1
    const int arow  = lane & 15, acol = lane >> 4;

    for (int q = 0; q < 4; q++) {
        cp_wait0();
        __syncthreads();   // staging q + A q ready; all prior MMA done

        // ---- convert staging x[k][n] float -> Bt[n][k] bf16 hi/lo (pitch 136) ----
#pragma unroll
        for (int j = 0; j < 8; j++) {
            const int ko = 2 * j + chalf;          // k-octet 0..15
            float v[8];
#pragma unroll
            for (int e = 0; e < 8; e++)
                v[e] = sm[(ko * 8 + e) * 132 + cn];
            __nv_bfloat162 h[4], l[4];
#pragma unroll
            for (int p = 0; p < 4; p++) {
                h[p] = __floats2bfloat162_rn(v[2 * p], v[2 * p + 1]);
                float h0 = __bfloat162float(__low2bfloat16(h[p]));
                float h1 = __bfloat162float(__high2bfloat16(h[p]));
                l[p] = __floats2bfloat162_rn(v[2 * p] - h0, v[2 * p + 1] - h1);
            }
            uint4 uh = *(uint4*)h;
            uint4 ul = *(uint4*)l;
            *(uint4*)((char*)sm + BH_OFF + cn * 272 + ko * 16) = uh;
            *(uint4*)((char*)sm + BL_OFF + cn * 272 + ko * 16) = ul;
        }
        __syncthreads();

        // ---- prefetch next staging tile (Xs now free) ----
        if (q < 3) {
            const int k0 = (q + 1) * 128;
#pragma unroll
            for (int r = 0; r < 16; r++) {
                int id = t + r * 256;
                int row = id >> 5, f4 = id & 31;
                cpa16(smb + XS_OFF + (uint32_t)(row * 132 + f4 * 4) * 4,
                      xb + (size_t)(k0 + row) * NN + n0 + f4 * 4);
            }
            cp_commit();
        }

        // ---- MMA: 8 k16 steps, 3 split-products ----
#pragma unroll
        for (int kk = 0; kk < 8; kk++) {
            const uint32_t kbyte = (uint32_t)(kk * 16 + acol * 8) * 2;
            uint32_t bh[2][4], bl[2][4];
#pragma unroll
            for (int jj = 0; jj < 2; jj++) {
                const uint32_t baddr = (uint32_t)((wn * 32 + jj * 16 + arow) * 272) + kbyte;
                ldsm4(bh[jj][0], bh[jj][1], bh[jj][2], bh[jj][3], smb + BH_OFF + baddr);
                ldsm4(bl[jj][0], bl[jj][1], bl[jj][2], bl[jj][3], smb + BL_OFF + baddr);
            }
#pragma unroll
            for (int i = 0; i < 4; i++) {
                const uint32_t aaddr = (uint32_t)((wm * 64 + i * 16 + arow) * 272) + kbyte;
                uint32_t ah0, ah1, ah2, ah3, al0, al1, al2, al3;
                ldsm4(ah0, ah1, ah2, ah3, smb + AH_OFF + aaddr);
                ldsm4(al0, al1, al2, al3, smb + AL_OFF + aaddr);
#pragma unroll
                for (int j = 0; j < 4; j++) {
                    const int jj = j >> 1, jo = j & 1;
                    uint32_t bb0 = bh[jj][jo], bb1 = bh[jj][jo + 2];
                    uint32_t bc0 = bl[jj][jo], bc1 = bl[jj][jo + 2];
                    mma16816(acc[i][j], ah0, ah1, ah2, ah3, bb0, bb1);
                    mma16816(acc[i][j], ah0, ah1, ah2, ah3, bc0, bc1);
                    mma16816(acc[i][j], al0, al1, al2, al3, bb0, bb1);
                }
            }
        }

        // ---- A panels for next chunk (A buffers free after all warps pass) ----
        if (q < 3) {
            __syncthreads();
            const int k0 = (q + 1) * 128;
#pragma unroll
            for (int r = 0; r < 8; r++) {
                int id = t + r * 256;
                int row = id >> 4, seg = id & 15;
                cpa16(smb + AH_OFF + (uint32_t)(row * 136 + seg * 8) * 2,
                      g_Wh + row * CH + k0 + seg * 8);
                cpa16(smb + AL_OFF + (uint32_t)(row * 136 + seg * 8) * 2,
                      g_Wl + row * CH + k0 + seg * 8);
            }
            cp_commit();
        }
    }
    __syncthreads();   // all MMA done before Kf_s overwrites the A region

    // ---- epilogue: bias + delu; Q rows (wm=0) -> gmem, K rows (wm=1) -> smem ----
    float* Kf_s = sm + (AH_OFF / 4);   // [64][132]
    {
#pragma unroll
        for (int i = 0; i < 4; i++) {
#pragma unroll
            for (int h = 0; h < 2; h++) {
                const int rl = i * 16 + g + 8 * h;     // row within this wm group (0..63)
                const float bias = (wm == 0) ? bq[rl] : bk[rl];
#pragma unroll
                for (int j = 0; j < 4; j++) {
                    const int col = wn * 32 + j * 8 + 2 * tq;
                    float2 o;
                    o.x = delu(acc[i][j][2 * h] + bias);
                    o.y = delu(acc[i][j][2 * h + 1] + bias);
                    if (wm == 0) {
                        *(float2*)&g_Qf[((size_t)b * DD + rl) * NN + n0 + col] = o;
                    } else {
                        *(float2*)&Kf_s[rl * 132 + col] = o;
                    }
                }
            }
        }
    }
    __syncthreads();

    // ---- Ksum partials ----
    {
#pragma unroll
        for (int r = 0; r < 8; r++) {
            const int m = wid * 8 + r;
            float s = Kf_s[m * 132 + lane] + Kf_s[m * 132 + lane + 32]
                    + Kf_s[m * 132 + lane + 64] + Kf_s[m * 132 + lane + 96];
#pragma unroll
            for (int off = 16; off > 0; off >>= 1)
                s += __shfl_down_sync(0xffffffffu, s, off);
            if (lane == 0) atomicAdd(&g_Ksum[b * DD + m], s);
        }
    }

    // ---- phase 2: KXt += Kf_s @ x^T, 4 c-chunks of 128, micro 8m x 4c ----
    const int txc = t & 31, tym = t >> 5;
    for (int c0 = 0; c0 < CH; c0 += 128) {
        __syncthreads();
#pragma unroll
        for (int r = 0; r < 16; r++) {
            const int id = t + r * 256;
            const int c = id >> 5, nf = id & 31;
            *(float4*)&sm[c * 132 + nf * 4] =
                *(const float4*)&xb[(size_t)(c0 + c) * NN + n0 + nf * 4];
        }
        __syncthreads();

        float accP[8][4];
#pragma unroll
        for (int i = 0; i < 8; i++)
#pragma unroll
            for (int j = 0; j < 4; j++) accP[i][j] = 0.0f;

#pragma unroll 4
        for (int n4 = 0; n4 < 128; n4 += 4) {
            float4 X[4];
#pragma unroll
            for (int j = 0; j < 4; j++)
                X[j] = *(const float4*)&sm[(txc + 32 * j) * 132 + n4];
#pragma unroll
            for (int i = 0; i < 8; i++) {
                float4 K4 = *(const float4*)&Kf_s[(tym * 8 + i) * 132 + n4];
#pragma unroll
                for (int j = 0; j < 4; j++) {
                    accP[i][j] += K4.x * X[j].x;
                    accP[i][j] += K4.y * X[j].y;
                    accP[i][j] += K4.z * X[j].z;
                    accP[i][j] += K4.w * X[j].w;
                }
            }
        }
#pragma unroll
        for (int i = 0; i < 8; i++) {
            const int m = tym * 8 + i;
#pragma unroll
            for (int j = 0; j < 4; j++)
                atomicAdd(&g_KXt[((size_t)b * DD + m) * CH + c0 + txc + 32 * j], accP[i][j]);
        }
    }
}

// ---------------------------------------------------------------------------
// 2) KV = KXt_flat[512,512] @ wv^T + (Ksum-EPS)*bv.  K split into 16 chunks.
// ---------------------------------------------------------------------------
__global__ __launch_bounds__(256) void kv_kernel(
    const float* __restrict__ wv, const float* __restrict__ bv)
{
    __shared__ float As[32][65];
    __shared__ float Bs[32][129];
    const int e0 = blockIdx.x * 128;
    const int m0 = blockIdx.y * 64;
    const int c0 = blockIdx.z * 32;
    const int t  = threadIdx.x;
    const int tx = t & 31, ty = t >> 5;

    float acc[8][4];
#pragma unroll
    for (int i = 0; i < 8; i++)
#pragma unroll
        for (int j = 0; j < 4; j++) acc[i][j] = 0.0f;

    {
        const int k0 = c0;
#pragma unroll
        for (int r = 0; r < 8; r++) {
            int idx = t + r * 256;
            int m = idx >> 5, kk = idx & 31;
            As[kk][m] = g_KXt[(size_t)(m0 + m) * CH + k0 + kk];
        }
#pragma unroll
        for (int r = 0; r < 16; r++) {
            int idx = t + r * 256;
            int e = idx >> 5, kk = idx & 31;
            Bs[kk][e] = wv[(size_t)(e0 + e) * CH + k0 + kk];
        }
        __syncthreads();
#pragma unroll
        for (int kk = 0; kk < 32; kk++) {
            float a[8], bb[4];
#pragma unroll
            for (int i = 0; i < 8; i++) a[i] = As[kk][ty * 8 + i];
#pragma unroll
            for (int j = 0; j < 4; j++) bb[j] = Bs[kk][tx * 4 + j];
#pragma unroll
            for (int i = 0; i < 8; i++)
#pragma unroll
                for (int j = 0; j < 4; j++) acc[i][j] += a[i] * bb[j];
        }
    }

#pragma unroll
    for (int i = 0; i < 8; i++) {
        int m = m0 + ty * 8 + i;
#pragma unroll
        for (int j = 0; j < 4; j++) {
            int e = e0 + tx * 4 + j;
            float v = acc[i][j];
            if (blockIdx.z == 0) v += (g_Ksum[m] - EPSF) * bv[e];
            atomicAdd(&g_KV[(size_t)m * CH + e], v);
        }
    }
}

// ---------------------------------------------------------------------------
// 3) out = x + gamma * norm[n] * (Qf^T @ KV).  f32x2, tile c128 x n256, K=64.
// ---------------------------------------------------------------------------
__global__ __launch_bounds__(512) void out_kernel(
    const float* __restrict__ x, const float* __restrict__ gamma,
    float* __restrict__ out)
{
    extern __shared__ float sm[];
    float* Qs    = sm;
    float* Vs    = sm + 16640;
    float* Ks    = sm + 25088;
    float* normv = sm + 25152;

    const int b  = blockIdx.z;
    const int c0 = blockIdx.y * 128;
    const int n0 = blockIdx.x * 256;
    const int t  = threadIdx.x;
    const float* qf = g_Qf + (size_t)b * DD * NN;
    const float* kv = g_KV + (size_t)b * DD * CH;

#pragma unroll
    for (int r = 0; r < 8; r++) {
        const int id = t + r * 512;
        const int d = id >> 6, nf = id & 63;
        *(float4*)&Qs[d * 260 + nf * 4] = *(const float4*)&qf[(size_t)d * NN + n0 + nf * 4];
    }
#pragma unroll
    for (int r = 0; r < 4; r++) {
        const int id = t + r * 512;
        const int d = id >> 5, cf = id & 31;
        *(float4*)&Vs[d * 132 + cf * 4] = *(const float4*)&kv[(size_t)d * CH + c0 + cf * 4];
    }
    if (t < 64) Ks[t] = g_Ksum[b * DD + t];
    __syncthreads();

    if (t < 256) {
        float s = 0.0f;
#pragma unroll
        for (int d = 0; d < 64; d++) s += Qs[d * 260 + t] * Ks[d];
        normv[t] = 1.0f / s;
    }
    __syncthreads();

    const int tx = t & 31, tyc = t >> 5;
    ull acc2[8][4];
#pragma unroll
    for (int i = 0; i < 8; i++)
#pragma unroll
        for (int j = 0; j < 4; j++) acc2[i][j] = 0ull;

#pragma unroll 4
    for (int d = 0; d < 64; d++) {
        double2 Qa = *(const double2*)&Qs[d * 260 + tx * 4];
        double2 Qb = *(const double2*)&Qs[d * 260 + tx * 4 + 128];
        float4 V0 = *(const float4*)&Vs[d * 132 + tyc * 8];
        float4 V1 = *(const float4*)&Vs[d * 132 + tyc * 8 + 4];
        ull qa0 = d2u(Qa.x), qa1 = d2u(Qa.y), qb0 = d2u(Qb.x), qb1 = d2u(Qb.y);
        float vv[8] = {V0.x, V0.y, V0.z, V0.w, V1.x, V1.y, V1.z, V1.w};
#pragma unroll
        for (int i = 0; i < 8; i++) {
            ull vd = dup2(vv[i]);
            fma2(acc2[i][0], vd, qa0);
            fma2(acc2[i][1], vd, qa1);
            fma2(acc2[i][2], vd, qb0);
            fma2(acc2[i][3], vd, qb1);
        }
    }

    const float g = gamma[0];
    float4 nva = *(const float4*)&normv[tx * 4];
    float4 nvb = *(const float4*)&normv[tx * 4 + 128];
#pragma unroll
    for (int i = 0; i < 8; i++) {
        const int cc = c0 + tyc * 8 + i;
        const size_t base = ((size_t)b * CH + cc) * NN + n0;
        float2 p0 = unpk(acc2[i][0]), p1 = unpk(acc2[i][1]);
        float2 p2 = unpk(acc2[i][2]), p3 = unpk(acc2[i][3]);
        float4 xa = *(const float4*)&x[base + tx * 4];
        float4 xb2 = *(const float4*)&x[base + tx * 4 + 128];
        float4 oa, ob;
        oa.x = xa.x + g * nva.x * p0.x;
        oa.y = xa.y + g * nva.y * p0.y;
        oa.z = xa.z + g * nva.z * p1.x;
        oa.w = xa.w + g * nva.w * p1.y;
        ob.x = xb2.x + g * nvb.x * p2.x;
        ob.y = xb2.y + g * nvb.y * p2.y;
        ob.z = xb2.z + g * nvb.z * p3.x;
        ob.w = xb2.w + g * nvb.w * p3.y;
        *(float4*)&out[base + tx * 4] = oa;
        *(float4*)&out[base + tx * 4 + 128] = ob;
    }
}

// ---------------------------------------------------------------------------
extern "C" void kernel_launch(void* const* d_in, const int* in_sizes, int n_in,
                              void* d_out, int out_size)
{
    const float* x     = (const float*)d_in[0];
    const float* wq    = (const float*)d_in[1];
    const float* bq    = (const float*)d_in[2];
    const float* wk    = (const float*)d_in[3];
    const float* bk    = (const float*)d_in[4];
    const float* wv    = (const float*)d_in[5];
    const float* bv    = (const float*)d_in[6];
    const float* gamma = (const float*)d_in[7];
    float* out = (float*)d_out;

    static bool attr_done = false;
    if (!attr_done) {
        cudaFuncSetAttribute(qk_kxt_kernel, cudaFuncAttributeMaxDynamicSharedMemorySize,
                             SMEM_TOT);
        cudaFuncSetAttribute(out_kernel, cudaFuncAttributeMaxDynamicSharedMemorySize,
                             25408 * (int)sizeof(float));
        attr_done = true;
    }

    init_kernel<<<(BATCH * DD * CH + 255) / 256, 256>>>(wq, wk);
    qk_kxt_kernel<<<dim3(NN / 128, BATCH), 256, SMEM_TOT>>>(x, bq, bk);
    kv_kernel<<<dim3(CH / 128, (BATCH * DD) / 64, 16), 256>>>(wv, bv);
    out_kernel<<<dim3(NN / 256, CH / 128, BATCH), 512, 25408 * sizeof(float)>>>(x, gamma, out);
}